// round 1
// baseline (speedup 1.0000x reference)
#include <cuda_runtime.h>

#define TPB 256

#define NBATCH 2048
#define CDIM 192
#define NPOS 64
#define NHEAD 6
#define HCH 32
#define NGRP 3
#define GCH 64
#define NS 16
#define RS 68      // row stride for [C][64] tiles (float4-aligned, conflict-light)
#define RSW 196    // row stride for staged weight chunk [64][192]
#define RS2 17     // row stride for [C][16] tiles

// shared-memory layout (float offsets)
#define O_XS    0          // 192*68 = 13056  (x, later reused for attn-output)
#define O_QS    13056      // 13056
#define O_WBUF  26112      // 64*196 = 12544 (padded region 13056)
#define O_SAMP  39168      // 192*17 = 3264
#define O_KS    42432      // 3264
#define O_VS    45696      // 3264
#define O_RPE   48960      // 6*15*15 = 1350
#define O_DWW   50310      // 64*9 = 576
#define O_DWB   50886      // 64
#define O_LNG   50950      // 64
#define O_LNB   51014      // 64
#define O_PWW   51078      // 128
#define O_POS   51206      // 48*2
#define O_SMPW  51302      // 48*4
#define O_SMPI  51494      // 48*4 (ints)
#define SMEMF   51686
#define SMEM_BYTES (SMEMF * 4)

#define Y_SIZE   (NBATCH * CDIM * NPOS)   // 25165824
#define PR_SIZE  (NBATCH * NGRP * NS * 2) // 196608
#define POS_OFF  Y_SIZE
#define REF_OFF  (Y_SIZE + PR_SIZE)

__device__ __forceinline__ void stage_w(const float* __restrict__ W, int co0,
                                        float* __restrict__ sm, int tid)
{
    // stage 64 output rows of W (192 cols each) into wbuf[i][c]
    for (int t = tid; t < 64 * 192; t += TPB) {
        int i = t / 192;
        int c = t - i * 192;
        sm[O_WBUF + i * RSW + c] = W[(co0 + i) * 192 + c];
    }
}

// 192x64 output GEMM, K=192: out[co][p] = bias[co] + sum_c W[co][c]*in[c][p]
template <bool TO_SMEM>
__device__ __forceinline__ void gemm_big(const float* __restrict__ W, const float* __restrict__ bias,
                                         int inOff, int outOff, float* __restrict__ gout,
                                         float* __restrict__ sm, int tid)
{
    const int cob = tid >> 4;        // 0..15 -> 4 co rows each
    const int p = (tid & 15) * 4;    // 4 positions
    for (int chunk = 0; chunk < 3; ++chunk) {
        const int co0 = chunk * 64;
        stage_w(W, co0, sm, tid);
        __syncthreads();
        const int co = cob * 4;
        float acc[4][4];
#pragma unroll
        for (int i = 0; i < 4; ++i) {
            float bb = bias[co0 + co + i];
#pragma unroll
            for (int j = 0; j < 4; ++j) acc[i][j] = bb;
        }
        const float* w0 = &sm[O_WBUF + (co + 0) * RSW];
        const float* w1 = &sm[O_WBUF + (co + 1) * RSW];
        const float* w2 = &sm[O_WBUF + (co + 2) * RSW];
        const float* w3 = &sm[O_WBUF + (co + 3) * RSW];
#pragma unroll 4
        for (int c = 0; c < 192; ++c) {
            float4 xv = *(const float4*)&sm[inOff + c * RS + p];
            float r0 = w0[c], r1 = w1[c], r2 = w2[c], r3 = w3[c];
            acc[0][0] += r0 * xv.x; acc[0][1] += r0 * xv.y; acc[0][2] += r0 * xv.z; acc[0][3] += r0 * xv.w;
            acc[1][0] += r1 * xv.x; acc[1][1] += r1 * xv.y; acc[1][2] += r1 * xv.z; acc[1][3] += r1 * xv.w;
            acc[2][0] += r2 * xv.x; acc[2][1] += r2 * xv.y; acc[2][2] += r2 * xv.z; acc[2][3] += r2 * xv.w;
            acc[3][0] += r3 * xv.x; acc[3][1] += r3 * xv.y; acc[3][2] += r3 * xv.z; acc[3][3] += r3 * xv.w;
        }
#pragma unroll
        for (int i = 0; i < 4; ++i) {
            float4 v = make_float4(acc[i][0], acc[i][1], acc[i][2], acc[i][3]);
            if (TO_SMEM) {
                *(float4*)&sm[outOff + (co0 + co + i) * RS + p] = v;
            } else {
                *(float4*)&gout[(co0 + co + i) * 64 + p] = v;
            }
        }
        __syncthreads();
    }
}

// 192x16 output GEMM, K=192: out[co][s] = bias[co] + sum_c W[co][c]*samp[c][s]
__device__ __forceinline__ void gemm_small(const float* __restrict__ W, const float* __restrict__ bias,
                                           int outOff, float* __restrict__ sm, int tid)
{
    const int cob = tid >> 4;
    const int s = tid & 15;
    for (int chunk = 0; chunk < 3; ++chunk) {
        const int co0 = chunk * 64;
        stage_w(W, co0, sm, tid);
        __syncthreads();
        const int co = cob * 4;
        float acc[4];
#pragma unroll
        for (int i = 0; i < 4; ++i) acc[i] = bias[co0 + co + i];
        const float* w0 = &sm[O_WBUF + (co + 0) * RSW];
        const float* w1 = &sm[O_WBUF + (co + 1) * RSW];
        const float* w2 = &sm[O_WBUF + (co + 2) * RSW];
        const float* w3 = &sm[O_WBUF + (co + 3) * RSW];
#pragma unroll 4
        for (int c = 0; c < 192; ++c) {
            float xv = sm[O_SAMP + c * RS2 + s];
            acc[0] += w0[c] * xv;
            acc[1] += w1[c] * xv;
            acc[2] += w2[c] * xv;
            acc[3] += w3[c] * xv;
        }
#pragma unroll
        for (int i = 0; i < 4; ++i) sm[outOff + (co0 + co + i) * RS2 + s] = acc[i];
        __syncthreads();
    }
}

__global__ void __launch_bounds__(TPB, 1)
dat_fused_kernel(const float* __restrict__ x,
                 const float* __restrict__ wq, const float* __restrict__ bq,
                 const float* __restrict__ wk, const float* __restrict__ bk,
                 const float* __restrict__ wv, const float* __restrict__ bv,
                 const float* __restrict__ wo, const float* __restrict__ bo,
                 const float* __restrict__ dww, const float* __restrict__ dwb,
                 const float* __restrict__ lng, const float* __restrict__ lnb,
                 const float* __restrict__ pww, const float* __restrict__ rpe,
                 float* __restrict__ out, int writePR)
{
    extern __shared__ float sm[];
    const int b = blockIdx.x;
    const int tid = threadIdx.x;

    // ---- stage x (transpose to [c][p]) and all small params ----
    const float* xb = x + (size_t)b * (NPOS * CDIM);
    for (int t = tid; t < NPOS * CDIM; t += TPB) {
        int p = t / CDIM;
        int c = t - p * CDIM;
        sm[O_XS + c * RS + p] = xb[t];
    }
    for (int t = tid; t < 1350; t += TPB) sm[O_RPE + t] = rpe[t];
    for (int t = tid; t < 576; t += TPB) sm[O_DWW + t] = dww[t];
    if (tid < 64) {
        sm[O_DWB + tid] = dwb[tid];
        sm[O_LNG + tid] = lng[tid];
        sm[O_LNB + tid] = lnb[tid];
    }
    if (tid >= 64 && tid < 192) sm[O_PWW + tid - 64] = pww[tid - 64];
    __syncthreads();

    // ---- q = Wq x + bq ----
    gemm_big<true>(wq, bq, O_XS, O_QS, nullptr, sm, tid);

    // ---- offset network: 48 items (group g, sample s), one item per warp at a time ----
    const int warp = tid >> 5, lane = tid & 31;
    for (int k = 0; k < 6; ++k) {
        const int item = warp * 6 + k;
        const int g = item >> 4;
        const int s = item & 15;
        const int si = s >> 2, sj = s & 3;
        const int ch0 = lane, ch1 = lane + 32;
        // depthwise 3x3 stride-2 conv, pad 1
        float v0 = sm[O_DWB + ch0];
        float v1 = sm[O_DWB + ch1];
        const int iy0 = 2 * si - 1, ix0 = 2 * sj - 1;
#pragma unroll
        for (int di = 0; di < 3; ++di) {
            int iy = iy0 + di;
            if (iy < 0 || iy > 7) continue;
#pragma unroll
            for (int dj = 0; dj < 3; ++dj) {
                int ix = ix0 + dj;
                if (ix < 0 || ix > 7) continue;
                float q0 = sm[O_QS + (g * 64 + ch0) * RS + iy * 8 + ix];
                float q1 = sm[O_QS + (g * 64 + ch1) * RS + iy * 8 + ix];
                v0 += sm[O_DWW + ch0 * 9 + di * 3 + dj] * q0;
                v1 += sm[O_DWW + ch1 * 9 + di * 3 + dj] * q1;
            }
        }
        // channel layernorm over 64
        float ssum = v0 + v1, ssq = v0 * v0 + v1 * v1;
#pragma unroll
        for (int o = 16; o > 0; o >>= 1) {
            ssum += __shfl_xor_sync(0xffffffffu, ssum, o);
            ssq += __shfl_xor_sync(0xffffffffu, ssq, o);
        }
        float mu = ssum * (1.0f / 64.0f);
        float var = ssq * (1.0f / 64.0f) - mu * mu;
        float rstd = rsqrtf(var + 1e-5f);
        v0 = (v0 - mu) * rstd * sm[O_LNG + ch0] + sm[O_LNB + ch0];
        v1 = (v1 - mu) * rstd * sm[O_LNG + ch1] + sm[O_LNB + ch1];
        // exact GELU
        v0 = 0.5f * v0 * (1.0f + erff(v0 * 0.70710678118654752f));
        v1 = 0.5f * v1 * (1.0f + erff(v1 * 0.70710678118654752f));
        // pointwise 64 -> 2
        float o0 = sm[O_PWW + ch0] * v0 + sm[O_PWW + ch1] * v1;
        float o1 = sm[O_PWW + 64 + ch0] * v0 + sm[O_PWW + 64 + ch1] * v1;
#pragma unroll
        for (int o = 16; o > 0; o >>= 1) {
            o0 += __shfl_xor_sync(0xffffffffu, o0, o);
            o1 += __shfl_xor_sync(0xffffffffu, o1, o);
        }
        if (lane == 0) {
            float offy = tanhf(o0) * (2.0f / 3.0f);   // tanh * (1/(Hk-1)) * ORF
            float offx = tanhf(o1) * (2.0f / 3.0f);
            float ry = (2 * si - 3) * 0.25f;          // ref points on 4x4
            float rx = (2 * sj - 3) * 0.25f;
            float py = offy + ry;
            float px = offx + rx;
            sm[O_POS + item * 2 + 0] = py;
            sm[O_POS + item * 2 + 1] = px;
            // bilinear metadata on 8x8, align_corners=True, zero padding
            float gx = (px + 1.0f) * 3.5f;
            float gy = (py + 1.0f) * 3.5f;
            float x0f = floorf(gx), y0f = floorf(gy);
            int jx0 = (int)x0f, jy0 = (int)y0f;
            float wx1 = gx - x0f, wy1 = gy - y0f;
            float wxs[2] = {1.0f - wx1, wx1};
            float wys[2] = {1.0f - wy1, wy1};
            int* smpI = (int*)sm;
#pragma unroll
            for (int n = 0; n < 4; ++n) {
                int xi = jx0 + (n & 1);
                int yi = jy0 + (n >> 1);
                bool val = (xi >= 0 && xi <= 7 && yi >= 0 && yi <= 7);
                sm[O_SMPW + item * 4 + n] = val ? wxs[n & 1] * wys[n >> 1] : 0.0f;
                smpI[O_SMPI + item * 4 + n] = val ? (yi * 8 + xi) : 0;
            }
            if (writePR) {
                size_t po = ((size_t)b * 48 + item) * 2;
                out[POS_OFF + po + 0] = py;
                out[POS_OFF + po + 1] = px;
                out[REF_OFF + po + 0] = ry;
                out[REF_OFF + po + 1] = rx;
            }
        }
    }
    __syncthreads();

    // ---- bilinear sample x at pos -> samp[c][s] ----
    for (int t = tid; t < CDIM * NS; t += TPB) {
        int c = t >> 4;
        int s = t & 15;
        int item = (c >> 6) * 16 + s;
        const float* wp = &sm[O_SMPW + item * 4];
        const int* ip = ((const int*)sm) + O_SMPI + item * 4;
        const float* row = &sm[O_XS + c * RS];
        sm[O_SAMP + c * RS2 + s] =
            wp[0] * row[ip[0]] + wp[1] * row[ip[1]] + wp[2] * row[ip[2]] + wp[3] * row[ip[3]];
    }
    __syncthreads();

    // ---- k, v projections on sampled features ----
    gemm_small(wk, bk, O_KS, sm, tid);
    gemm_small(wv, bv, O_VS, sm, tid);

    // ---- attention: per (head, query-position) item ----
    for (int it = tid; it < NHEAD * NPOS; it += TPB) {
        const int h = it >> 6;
        const int p = it & 63;
        const int g = h >> 1;
        float a[16];
#pragma unroll
        for (int s = 0; s < 16; ++s) a[s] = 0.0f;
#pragma unroll 4
        for (int c = 0; c < 32; ++c) {
            float qv = sm[O_QS + (h * 32 + c) * RS + p];
            const float* kr = &sm[O_KS + (h * 32 + c) * RS2];
#pragma unroll
            for (int s = 0; s < 16; ++s) a[s] += qv * kr[s];
        }
        const float scale = 0.17677669529663687f;  // 32^-0.5
        float qy = (2 * (p >> 3) - 7) * 0.125f;    // ref points on 8x8
        float qx = (2 * (p & 7) - 7) * 0.125f;
        const float* rpeh = &sm[O_RPE + h * 225];
        float mx = -1e30f;
#pragma unroll
        for (int s = 0; s < 16; ++s) {
            float py = sm[O_POS + (g * 16 + s) * 2 + 0];
            float px = sm[O_POS + (g * 16 + s) * 2 + 1];
            float dy = (qy - py) * 0.5f;
            float dx = (qx - px) * 0.5f;
            float gx = (dx + 1.0f) * 7.0f;          // align_corners on 15x15
            float gy = (dy + 1.0f) * 7.0f;
            float x0f = floorf(gx), y0f = floorf(gy);
            int jx0 = (int)x0f, jy0 = (int)y0f;
            float wx1 = gx - x0f, wy1 = gy - y0f;
            float bias = 0.0f;
            if (jx0 >= 0 && jx0 <= 14 && jy0 >= 0 && jy0 <= 14)
                bias += (1.0f - wx1) * (1.0f - wy1) * rpeh[jy0 * 15 + jx0];
            if (jx0 + 1 >= 0 && jx0 + 1 <= 14 && jy0 >= 0 && jy0 <= 14)
                bias += wx1 * (1.0f - wy1) * rpeh[jy0 * 15 + jx0 + 1];
            if (jx0 >= 0 && jx0 <= 14 && jy0 + 1 >= 0 && jy0 + 1 <= 14)
                bias += (1.0f - wx1) * wy1 * rpeh[(jy0 + 1) * 15 + jx0];
            if (jx0 + 1 >= 0 && jx0 + 1 <= 14 && jy0 + 1 >= 0 && jy0 + 1 <= 14)
                bias += wx1 * wy1 * rpeh[(jy0 + 1) * 15 + jx0 + 1];
            a[s] = a[s] * scale + bias;
            mx = fmaxf(mx, a[s]);
        }
        float ssum = 0.0f;
#pragma unroll
        for (int s = 0; s < 16; ++s) { a[s] = __expf(a[s] - mx); ssum += a[s]; }
        float inv = 1.0f / ssum;
#pragma unroll
        for (int s = 0; s < 16; ++s) a[s] *= inv;
        // out[c][p] = sum_s a[s] * v[c][s]  (write into XS region, x no longer needed)
        for (int cl = 0; cl < 32; ++cl) {
            int c = h * 32 + cl;
            const float* vr = &sm[O_VS + c * RS2];
            float acc = 0.0f;
#pragma unroll
            for (int s = 0; s < 16; ++s) acc += a[s] * vr[s];
            sm[O_XS + c * RS + p] = acc;
        }
    }
    __syncthreads();

    // ---- y = Wo out + bo (direct to gmem) ----
    gemm_big<false>(wo, bo, O_XS, 0, out + (size_t)b * (CDIM * NPOS), sm, tid);
}

extern "C" void kernel_launch(void* const* d_in, const int* in_sizes, int n_in,
                              void* d_out, int out_size)
{
    (void)in_sizes; (void)n_in;
    const float* x   = (const float*)d_in[0];
    const float* wq  = (const float*)d_in[1];
    const float* bq  = (const float*)d_in[2];
    const float* wk  = (const float*)d_in[3];
    const float* bk  = (const float*)d_in[4];
    const float* wv  = (const float*)d_in[5];
    const float* bv  = (const float*)d_in[6];
    const float* wo  = (const float*)d_in[7];
    const float* bo  = (const float*)d_in[8];
    const float* dww = (const float*)d_in[9];
    const float* dwb = (const float*)d_in[10];
    const float* lng = (const float*)d_in[11];
    const float* lnb = (const float*)d_in[12];
    const float* pww = (const float*)d_in[13];
    const float* rpe = (const float*)d_in[14];
    float* out = (float*)d_out;

    int writePR = (out_size >= (REF_OFF + PR_SIZE)) ? 1 : 0;

    cudaFuncSetAttribute(dat_fused_kernel,
                         cudaFuncAttributeMaxDynamicSharedMemorySize, SMEM_BYTES);
    dat_fused_kernel<<<NBATCH, TPB, SMEM_BYTES>>>(
        x, wq, bq, wk, bk, wv, bv, wo, bo, dww, dwb, lng, lnb, pww, rpe, out, writePR);
}